// round 10
// baseline (speedup 1.0000x reference)
#include <cuda_runtime.h>
#include <cstdint>
#include <math.h>

// CausalGRNEMA fused single-pass (+ tiny init):
//  block = (b,k) chunk of LC=32 timesteps; x chunk and local scan trajectory
//  held in SMEM (128 KB). Carry-in via truncated lookback over predecessor
//  chunk aggregates (depth 40, alpha^(32*40) ~ 2.6e-6). Output phase uses
//  linearity f(t) = f_local(t) + alpha^(t+1)*E -> warp-per-2-timesteps,
//  warp-internal channel mean, no per-timestep barriers.
// State scaled: f = ema/OMA, f' = alpha*f + x^2.

#define ALPHA   0.99f
#define OMA     0.01f
#define EPSF    1e-6f
#define E0F     0.01f          // EMAINIT/OMA

static constexpr int B   = 16;
static constexpr int T   = 8192;
static constexpr int C   = 512;
static constexpr int C4  = C / 4;
static constexpr int LC  = 32;            // timesteps per block chunk
static constexpr int NCH = T / LC;        // 256 chunks per batch
static constexpr int NTASK = B * NCH;     // 4096 blocks
static constexpr int DEPTH = 40;          // lookback depth (a32^40 ~ 2.6e-6)
static constexpr float A32 = 0.7249804f;  // alpha^32
static constexpr float LNA = -0.01005034f; // ln(alpha)

__device__ float2 g_tab[T];               // (EPS*D_t, EPS*sqrt(D_t))
__device__ float  g_S[NTASK * C];         // chunk aggregates (f-units)
__device__ int    g_flag[NTASK];

// smem layout (floats): x[32*512] | f_local[32*512] | E[512] | gamma[512] | beta[512] | tab[32]*2
static constexpr int SM_X   = 0;
static constexpr int SM_F   = 32 * 512;
static constexpr int SM_E   = 64 * 512;
static constexpr int SM_G   = SM_E + 512;
static constexpr int SM_B   = SM_G + 512;
static constexpr int SM_TAB = SM_B + 512;          // 32 float2
static constexpr int SMEM_FLOATS = SM_TAB + 64;
static constexpr int SMEM_BYTES  = SMEM_FLOATS * 4;   // ~138 KB

__global__ void init_kernel() {
    int t = blockIdx.x * blockDim.x + threadIdx.x;
    if (t < T) {
        double D = 1.0 - exp((double)(t + 1) * log(0.99)) + 1e-6;
        g_tab[t] = make_float2((float)(1e-6 * D), (float)(1e-6 * sqrt(D)));
    }
    if (t < NTASK) g_flag[t] = 0;
}

__global__ __launch_bounds__(512, 1)
void fused_kernel(const float* __restrict__ x,
                  const float* __restrict__ gamma,
                  const float* __restrict__ beta,
                  float* __restrict__ y) {
    extern __shared__ float sm[];
    const int tid = threadIdx.x;
    const int k = blockIdx.x / B;         // k-major: predecessors have smaller bid
    const int b = blockIdx.x % B;
    const int task = b * NCH + k;
    const int tbase = k * LC;

    // ---- phase A: cooperative load chunk + params ----
    {
        const float4* gx = (const float4*)x + ((size_t)b * T + tbase) * C4;
        float4* smx4 = (float4*)(sm + SM_X);
        #pragma unroll
        for (int i = 0; i < 8; i++) smx4[tid + i * 512] = gx[tid + i * 512];

        if (tid < 128)      ((float4*)(sm + SM_G))[tid] = ((const float4*)gamma)[tid];
        else if (tid < 256) ((float4*)(sm + SM_B))[tid - 128] = ((const float4*)beta)[tid - 128];
        else if (tid < 288) ((float2*)(sm + SM_TAB))[tid - 256] = g_tab[tbase + (tid - 256)];
    }
    __syncthreads();

    // thread-per-channel local scan from 0, store trajectory
    {
        const int c = tid;
        float f = 0.0f;
        #pragma unroll
        for (int t = 0; t < LC; t++) {
            const float xx = sm[SM_X + t * 512 + c];
            f = fmaf(ALPHA, f, xx * xx);
            sm[SM_F + t * 512 + c] = f;
        }
        g_S[(size_t)task * C + c] = f;    // publish aggregate
    }
    __threadfence();
    __syncthreads();
    if (tid == 0) *((volatile int*)&g_flag[task]) = 1;

    // ---- lookback: E = P_{k-1} per channel (truncated) ----
    {
        const int jstart = (k > DEPTH) ? (k - DEPTH) : 0;
        float E = (jstart == 0) ? E0F : 0.0f;
        for (int j = jstart; j < k; j++) {
            volatile int* fl = &g_flag[b * NCH + j];
            while (*fl == 0) __nanosleep(64);
        }
        __threadfence();
        const float* Sb = g_S + (size_t)b * NCH * C + tid;
        for (int j = jstart; j < k; j++)
            E = fmaf(A32, E, Sb[(size_t)j * C]);
        sm[SM_E + tid] = E;
    }
    __syncthreads();

    // ---- phase C: warp w handles timesteps 2w, 2w+1 ----
    const int warp = tid >> 5;
    const int lane = tid & 31;
    const float4* smE4 = (const float4*)(sm + SM_E);
    const float4* smg4 = (const float4*)(sm + SM_G);
    const float4* smb4 = (const float4*)(sm + SM_B);

    #pragma unroll
    for (int tt = 0; tt < 2; tt++) {
        const int t = warp * 2 + tt;
        const float2 cs = ((const float2*)(sm + SM_TAB))[t];
        const float pa = __expf((float)(t + 1) * LNA);   // alpha^(t+1)

        const float4* fl4 = (const float4*)(sm + SM_F + t * 512);
        float4 s[4];
        float acc = 0.0f;
        #pragma unroll
        for (int j = 0; j < 4; j++) {
            const float4 fl = fl4[lane + j * 32];
            const float4 e4 = smE4[lane + j * 32];
            float fx = fmaf(pa, e4.x, fl.x);
            float fy = fmaf(pa, e4.y, fl.y);
            float fz = fmaf(pa, e4.z, fl.z);
            float fw = fmaf(pa, e4.w, fl.w);
            float vx = fmaf(OMA, fx, cs.x);
            float vy = fmaf(OMA, fy, cs.x);
            float vz = fmaf(OMA, fz, cs.x);
            float vw = fmaf(OMA, fw, cs.x);
            s[j].x = __frsqrt_rn(vx) * vx;
            s[j].y = __frsqrt_rn(vy) * vy;
            s[j].z = __frsqrt_rn(vz) * vz;
            s[j].w = __frsqrt_rn(vw) * vw;
            acc += (s[j].x + s[j].y) + (s[j].z + s[j].w);
        }
        acc += __shfl_xor_sync(0xffffffffu, acc, 16);
        acc += __shfl_xor_sync(0xffffffffu, acc, 8);
        acc += __shfl_xor_sync(0xffffffffu, acc, 4);
        acc += __shfl_xor_sync(0xffffffffu, acc, 2);
        acc += __shfl_xor_sync(0xffffffffu, acc, 1);

        const float inv = __fdividef(1.0f, fmaf(acc, 1.0f / C, cs.y));

        const float4* x4 = (const float4*)(sm + SM_X + t * 512);
        float4* yb = (float4*)y + ((size_t)b * T + tbase + t) * C4;
        #pragma unroll
        for (int j = 0; j < 4; j++) {
            const float4 xv = x4[lane + j * 32];
            const float4 g4 = smg4[lane + j * 32];
            const float4 b4 = smb4[lane + j * 32];
            float4 o;
            o.x = fmaf(xv.x, fmaf(g4.x, s[j].x * inv, 1.0f), b4.x);
            o.y = fmaf(xv.y, fmaf(g4.y, s[j].y * inv, 1.0f), b4.y);
            o.z = fmaf(xv.z, fmaf(g4.z, s[j].z * inv, 1.0f), b4.z);
            o.w = fmaf(xv.w, fmaf(g4.w, s[j].w * inv, 1.0f), b4.w);
            yb[lane + j * 32] = o;
        }
    }
}

extern "C" void kernel_launch(void* const* d_in, const int* in_sizes, int n_in,
                              void* d_out, int out_size) {
    const float* x     = (const float*)d_in[0];
    const float* gamma = (const float*)d_in[1];
    const float* beta  = (const float*)d_in[2];
    float* y           = (float*)d_out;

    static int smem_set = 0;
    if (!smem_set) {
        cudaFuncSetAttribute(fused_kernel,
                             cudaFuncAttributeMaxDynamicSharedMemorySize, SMEM_BYTES);
        smem_set = 1;
    }

    init_kernel<<<(T + 255) / 256, 256>>>();
    fused_kernel<<<NTASK, 512, SMEM_BYTES>>>(x, gamma, beta, y);
}

// round 12
// speedup vs baseline: 1.6626x; 1.6626x over previous
#include <cuda_runtime.h>
#include <cstdint>
#include <math.h>

// CausalGRNEMA exact chunked scan (R4 bodies, fixed scheduling):
//  pass1: LC1=64 warp chunks (WPB=7 -> grid 293 ~ full 148-SM single wave);
//         stores cumulative snapshots f(16),f(32),f(48),f(64) per chunk.
//  pass2: exact carry-ins at 16-step granularity:
//         Ein(k,q) = a16^q * E_k + f_cum(16q)   (no subtraction, exact)
//  pass3: LC3=16 -> 8192 warp tasks, grid 1024 -> full coverage + fine balance.
// State scaled: f = ema/OMA, f' = alpha*f + x^2.

#define ALPHA   0.99f
#define OMA     0.01f
#define EPSF    1e-6f
#define E0F     0.01f                     // EMAINIT/OMA

static constexpr int B    = 16;
static constexpr int T    = 8192;
static constexpr int C    = 512;
static constexpr int C4   = C / 4;        // 128 float4 columns
static constexpr int LC1  = 64;           // pass1 chunk
static constexpr int NCH1 = T / LC1;      // 128
static constexpr int LC3  = 16;           // pass3 chunk
static constexpr int NCH3 = T / LC3;      // 512
static constexpr int WPB1 = 7;            // pass1 warps/block (grid 293 ~ 296 slots)
static constexpr int WPB3 = 8;
static constexpr int NTASK1 = B * NCH1;   // 2048
static constexpr int NTASK3 = B * NCH3;   // 8192
static constexpr int GRID1  = (NTASK1 + WPB1 - 1) / WPB1;   // 293
static constexpr int GRID3  = NTASK3 / WPB3;                // 1024

__device__ float2 g_tab[T];               // (EPS*D_t, EPS*sqrt(D_t))
__device__ float  g_S[NTASK3 * C];        // cumulative snapshots (f-units), 16MB
__device__ float  g_Ein[NTASK3 * C];      // exact carry-in per 16-chunk, 16MB

// ---- pass1: warp-autonomous local scan, 4 cumulative snapshots ----
__global__ __launch_bounds__(224, 2)
void pass1_kernel(const float* __restrict__ x) {
    const int warp = threadIdx.x >> 5;
    const int lane = threadIdx.x & 31;
    const int task = blockIdx.x * WPB1 + warp;
    if (task >= NTASK1) return;
    const int b = task >> 7;              // / NCH1
    const int k = task & (NCH1 - 1);

    const float4* __restrict__ xb =
        (const float4*)x + ((size_t)b * T + (size_t)k * LC1) * C4 + lane;
    // snapshot q lives at linear 16-chunk index b*512 + k*4 + q
    float4* __restrict__ S4 =
        (float4*)g_S + (size_t)(b * NCH3 + k * 4) * C4 + lane;

    float4 f[4], cur[4], nxt[4];
    #pragma unroll
    for (int j = 0; j < 4; j++) f[j] = make_float4(0.f, 0.f, 0.f, 0.f);
    #pragma unroll
    for (int j = 0; j < 4; j++) cur[j] = xb[j * 32];

    for (int t = 0; t < LC1; t++) {
        if (t + 1 < LC1) {
            #pragma unroll
            for (int j = 0; j < 4; j++) nxt[j] = xb[(size_t)(t + 1) * C4 + j * 32];
        }
        #pragma unroll
        for (int j = 0; j < 4; j++) {
            f[j].x = fmaf(ALPHA, f[j].x, cur[j].x * cur[j].x);
            f[j].y = fmaf(ALPHA, f[j].y, cur[j].y * cur[j].y);
            f[j].z = fmaf(ALPHA, f[j].z, cur[j].z * cur[j].z);
            f[j].w = fmaf(ALPHA, f[j].w, cur[j].w * cur[j].w);
        }
        if ((t & 15) == 15) {             // cumulative snapshot q = t>>4
            const int q = t >> 4;
            #pragma unroll
            for (int j = 0; j < 4; j++) S4[(size_t)q * C4 + j * 32] = f[j];
        }
        #pragma unroll
        for (int j = 0; j < 4; j++) cur[j] = nxt[j];
    }
}

// ---- pass2: build g_tab + exact carry-ins at 16-step granularity ----
__global__ void pass2_kernel() {
    const int idx = blockIdx.x * blockDim.x + threadIdx.x;  // 0..B*C-1 (== T)
    if (idx < T) {
        double D = 1.0 - exp((double)(idx + 1) * log(0.99)) + 1e-6;
        g_tab[idx] = make_float2((float)(1e-6 * D), (float)(1e-6 * sqrt(D)));
    }
    if (idx >= B * C) return;
    const int b = idx / C;
    const int c = idx % C;
    const float a16  = (float)exp(16.0 * log(0.99));
    const float a16_2 = a16 * a16;
    const float a16_3 = a16_2 * a16;
    const float a16_4 = a16_2 * a16_2;
    float E = E0F;                        // f-units
    for (int k = 0; k < NCH1; k++) {
        const size_t o = ((size_t)b * NCH3 + 4 * k) * C + c;
        const float f16 = g_S[o];
        const float f32 = g_S[o + C];
        const float f48 = g_S[o + 2 * C];
        const float f64 = g_S[o + 3 * C];
        g_Ein[o]         = E;
        g_Ein[o + C]     = fmaf(a16,   E, f16);
        g_Ein[o + 2 * C] = fmaf(a16_2, E, f32);
        g_Ein[o + 3 * C] = fmaf(a16_3, E, f48);
        E = fmaf(a16_4, E, f64);
    }
}

// ---- pass3: warp-autonomous rescan (LC3=16) + warp-internal mean + epilogue ----
__global__ __launch_bounds__(256, 2)
void pass3_kernel(const float* __restrict__ x,
                  const float* __restrict__ gamma,
                  const float* __restrict__ beta,
                  float* __restrict__ y) {
    __shared__ float4 sg[C4], sb[C4];
    {
        const int tid = threadIdx.x;
        if (tid < C4)       sg[tid]      = ((const float4*)gamma)[tid];
        else                sb[tid - C4] = ((const float4*)beta)[tid - C4];
    }
    __syncthreads();   // once

    const int warp = threadIdx.x >> 5;
    const int lane = threadIdx.x & 31;
    const int task = blockIdx.x * WPB3 + warp;
    const int b  = task >> 9;             // / NCH3 (=512)
    const int kq = task & (NCH3 - 1);
    const int tbase = kq * LC3;

    const float4* __restrict__ xb =
        (const float4*)x + ((size_t)b * T + tbase) * C4 + lane;
    float4* __restrict__ yb =
        (float4*)y + ((size_t)b * T + tbase) * C4 + lane;

    float4 f[4];
    {
        const float4* __restrict__ E4 = (const float4*)g_Ein + (size_t)task * C4 + lane;
        #pragma unroll
        for (int j = 0; j < 4; j++) f[j] = E4[j * 32];
    }

    float4 cur[4], nxt[4];
    #pragma unroll
    for (int j = 0; j < 4; j++) cur[j] = xb[j * 32];

    for (int t = 0; t < LC3; t++) {
        if (t + 1 < LC3) {
            #pragma unroll
            for (int j = 0; j < 4; j++) nxt[j] = xb[(size_t)(t + 1) * C4 + j * 32];
        }
        const float2 cs = g_tab[tbase + t];   // (EPS*D, EPS*sqrt(D))

        float4 s[4];
        float acc = 0.0f;
        #pragma unroll
        for (int j = 0; j < 4; j++) {
            f[j].x = fmaf(ALPHA, f[j].x, cur[j].x * cur[j].x);
            f[j].y = fmaf(ALPHA, f[j].y, cur[j].y * cur[j].y);
            f[j].z = fmaf(ALPHA, f[j].z, cur[j].z * cur[j].z);
            f[j].w = fmaf(ALPHA, f[j].w, cur[j].w * cur[j].w);
            float vx = fmaf(OMA, f[j].x, cs.x);
            float vy = fmaf(OMA, f[j].y, cs.x);
            float vz = fmaf(OMA, f[j].z, cs.x);
            float vw = fmaf(OMA, f[j].w, cs.x);
            s[j].x = __frsqrt_rn(vx) * vx;    // = sqrt(vx)
            s[j].y = __frsqrt_rn(vy) * vy;
            s[j].z = __frsqrt_rn(vz) * vz;
            s[j].w = __frsqrt_rn(vw) * vw;
            acc += (s[j].x + s[j].y) + (s[j].z + s[j].w);
        }
        acc += __shfl_xor_sync(0xffffffffu, acc, 16);
        acc += __shfl_xor_sync(0xffffffffu, acc, 8);
        acc += __shfl_xor_sync(0xffffffffu, acc, 4);
        acc += __shfl_xor_sync(0xffffffffu, acc, 2);
        acc += __shfl_xor_sync(0xffffffffu, acc, 1);

        // n_c = s_c / (mean + EPS*sqrt(D)); y = x*(1 + gamma*n) + beta
        const float inv = __fdividef(1.0f, fmaf(acc, 1.0f / C, cs.y));

        #pragma unroll
        for (int j = 0; j < 4; j++) {
            const float4 g4 = sg[lane + j * 32];
            const float4 b4 = sb[lane + j * 32];
            float4 o;
            o.x = fmaf(cur[j].x, fmaf(g4.x, s[j].x * inv, 1.0f), b4.x);
            o.y = fmaf(cur[j].y, fmaf(g4.y, s[j].y * inv, 1.0f), b4.y);
            o.z = fmaf(cur[j].z, fmaf(g4.z, s[j].z * inv, 1.0f), b4.z);
            o.w = fmaf(cur[j].w, fmaf(g4.w, s[j].w * inv, 1.0f), b4.w);
            yb[(size_t)t * C4 + j * 32] = o;
        }
        #pragma unroll
        for (int j = 0; j < 4; j++) cur[j] = nxt[j];
    }
}

extern "C" void kernel_launch(void* const* d_in, const int* in_sizes, int n_in,
                              void* d_out, int out_size) {
    const float* x     = (const float*)d_in[0];
    const float* gamma = (const float*)d_in[1];
    const float* beta  = (const float*)d_in[2];
    float* y           = (float*)d_out;

    pass1_kernel<<<GRID1, WPB1 * 32>>>(x);
    pass2_kernel<<<(B * C + 255) / 256, 256>>>();
    pass3_kernel<<<GRID3, 256>>>(x, gamma, beta, y);
}